// round 7
// baseline (speedup 1.0000x reference)
#include <cuda_runtime.h>

// ChamferLoss: f[4,8192,3], f_[4,8192,3] -> scalar.
// R7: both directions computed independently (R4 structure, row-mins in
// registers only), with the sign-folded 3-FMA math from R5:
//   tile stores (-2x,-2y),(-2z,w) packed over dst pairs, w=||p||^2,
//   h = fma(-2z,sz, fma(-2y,sy, fma(-2x,sx, w))) ; min over dst ; + s^2 ; clamp.
// 256 threads (2 warps/SMSP for latency hiding) x 2 src/thread, 128 blocks.

namespace {
constexpr int kB = 4;
constexpr int kN = 8192;
constexpr int kThreads = 256;
constexpr int kSrcPerThread = 2;
constexpr int kSrcPerBlock = kThreads * kSrcPerThread;  // 512
constexpr int kChunks = kN / kSrcPerBlock;              // 16
constexpr int kBlocks = kChunks * kB * 2;               // 128
constexpr int kTile = 2048;                             // dst points per smem tile
constexpr int kPairs = kTile / 2;                       // 1024 packed dst pairs
constexpr int kTiles = kN / kTile;                      // 4
constexpr float kBig = 3.4e38f;
}  // namespace

__device__ float g_partials[kBlocks];
__device__ float g_p2[4];

__device__ __forceinline__ unsigned long long pack2(float lo, float hi) {
    unsigned long long r;
    asm("mov.b64 %0, {%1, %2};" : "=l"(r) : "f"(lo), "f"(hi));
    return r;
}
__device__ __forceinline__ void unpack2(unsigned long long v, float& lo, float& hi) {
    asm("mov.b64 {%0, %1}, %2;" : "=f"(lo), "=f"(hi) : "l"(v));
}
__device__ __forceinline__ unsigned long long fma2(unsigned long long a, unsigned long long b,
                                                   unsigned long long c) {
    unsigned long long d;
    asm("fma.rn.f32x2 %0, %1, %2, %3;" : "=l"(d) : "l"(a), "l"(b), "l"(c));
    return d;
}

__global__ void __launch_bounds__(kThreads, 1)
chamfer_pairs_kernel(const float* __restrict__ f, const float* __restrict__ f_) {
    // Paired dst tile, sign-folded:
    //   sA[jp] = {pack(-2x0,-2x1), pack(-2y0,-2y1)}
    //   sB[jp] = {pack(-2z0,-2z1), pack( w0,  w1)}   (w = ||p||^2)
    __shared__ ulonglong2 sA[kPairs];
    __shared__ ulonglong2 sB[kPairs];
    __shared__ float swsum[kThreads / 32];

    const int dir = blockIdx.z;
    const int b = blockIdx.y;
    const int chunk = blockIdx.x;

    const float* src = (dir == 0) ? f : f_;
    const float* dst = (dir == 0) ? f_ : f;
    src += (size_t)b * kN * 3;
    dst += (size_t)b * kN * 3;

    const int tid = threadIdx.x;

    // Src points: loop-invariant replicated packs + s^2.
    unsigned long long sxx[kSrcPerThread], syy[kSrcPerThread], szz[kSrcPerThread];
    float s2[kSrcPerThread];
    float m0[kSrcPerThread], m1[kSrcPerThread];
#pragma unroll
    for (int i = 0; i < kSrcPerThread; ++i) {
        const int n = chunk * kSrcPerBlock + i * kThreads + tid;
        const float x = src[n * 3 + 0];
        const float y = src[n * 3 + 1];
        const float z = src[n * 3 + 2];
        sxx[i] = pack2(x, x);
        syy[i] = pack2(y, y);
        szz[i] = pack2(z, z);
        s2[i] = fmaf(z, z, fmaf(y, y, x * x));
        m0[i] = kBig;
        m1[i] = kBig;
    }

    for (int t = 0; t < kTiles; ++t) {
        const float* dt = dst + (size_t)t * kTile * 3;
        for (int jp = tid; jp < kPairs; jp += kThreads) {
            const float x0 = dt[jp * 6 + 0];
            const float y0 = dt[jp * 6 + 1];
            const float z0 = dt[jp * 6 + 2];
            const float x1 = dt[jp * 6 + 3];
            const float y1 = dt[jp * 6 + 4];
            const float z1 = dt[jp * 6 + 5];
            const float w0 = fmaf(z0, z0, fmaf(y0, y0, x0 * x0));
            const float w1 = fmaf(z1, z1, fmaf(y1, y1, x1 * x1));
            sA[jp] = make_ulonglong2(pack2(-2.0f * x0, -2.0f * x1),
                                     pack2(-2.0f * y0, -2.0f * y1));
            sB[jp] = make_ulonglong2(pack2(-2.0f * z0, -2.0f * z1),
                                     pack2(w0, w1));
        }
        __syncthreads();

#pragma unroll 8
        for (int jp = 0; jp < kPairs; ++jp) {
            const ulonglong2 A = sA[jp];  // LDS.128 broadcast, conflict-free
            const ulonglong2 B = sB[jp];
#pragma unroll
            for (int i = 0; i < kSrcPerThread; ++i) {
                unsigned long long c = fma2(A.x, sxx[i], B.y);  // w - 2x*sx
                c = fma2(A.y, syy[i], c);                       // .. - 2y*sy
                c = fma2(B.x, szz[i], c);                       // .. - 2z*sz
                float h0, h1;
                unpack2(c, h0, h1);
                m0[i] = fminf(m0[i], h0);
                m1[i] = fminf(m1[i], h1);
            }
        }
        __syncthreads();
    }

    float v = 0.0f;
#pragma unroll
    for (int i = 0; i < kSrcPerThread; ++i) {
        v += fmaxf(s2[i] + fminf(m0[i], m1[i]), 0.0f);
    }

#pragma unroll
    for (int off = 16; off > 0; off >>= 1) {
        v += __shfl_xor_sync(0xffffffffu, v, off);
    }
    const int lane = tid & 31;
    const int wid = tid >> 5;
    if (lane == 0) swsum[wid] = v;
    __syncthreads();
    if (tid == 0) {
        float s = 0.0f;
#pragma unroll
        for (int w = 0; w < kThreads / 32; ++w) s += swsum[w];
        g_partials[chunk + kChunks * (b + kB * dir)] = s;
    }
}

// Stage A: one block of 128 threads, 4 warps; warp w sums partials
// [32w, 32w+32) in a fixed shuffle order -> deterministic.
__global__ void chamfer_reduceA_kernel() {
    const int tid = threadIdx.x;  // 128
    float v = g_partials[tid];
#pragma unroll
    for (int off = 16; off > 0; off >>= 1) {
        v += __shfl_xor_sync(0xffffffffu, v, off);
    }
    if ((tid & 31) == 0) g_p2[tid >> 5] = v;
}

__global__ void chamfer_reduceB_kernel(float* __restrict__ out) {
    if (threadIdx.x == 0) {
        out[0] = ((g_p2[0] + g_p2[1]) + (g_p2[2] + g_p2[3])) / (float)(kN * kB);
    }
}

extern "C" void kernel_launch(void* const* d_in, const int* in_sizes, int n_in,
                              void* d_out, int out_size) {
    const float* f = (const float*)d_in[0];
    const float* f_ = (const float*)d_in[1];
    (void)in_sizes; (void)n_in; (void)out_size;

    dim3 grid(kChunks, kB, 2);
    chamfer_pairs_kernel<<<grid, kThreads>>>(f, f_);
    chamfer_reduceA_kernel<<<1, 128>>>();
    chamfer_reduceB_kernel<<<1, 32>>>((float*)d_out);
}

// round 8
// speedup vs baseline: 1.5478x; 1.5478x over previous
#include <cuda_runtime.h>

// ChamferLoss: f[4,8192,3], f_[4,8192,3] -> scalar.
// R8 = R4 structure exactly (best: 98.8us), with the final packed fma2(neg2)
// replaced by two scalar FFMA-imm (rt=1 vs rt=3 for 3-operand f32x2 ops):
//   cross = mul2 + fma2 + fma2            (2+3+3 = 8 cyc / 2 pairs)
//   h0 = fmaf(c0, -2.0f, w0)  [imm form]  (1 cyc)
//   h1 = fmaf(c1, -2.0f, w1)  [imm form]  (1 cyc)
// Unpacks are register renaming (no SASS). Mins ride the alu pipe.

namespace {
constexpr int kB = 4;
constexpr int kN = 8192;
constexpr int kThreads = 256;
constexpr int kSrcPerThread = 2;
constexpr int kSrcPerBlock = kThreads * kSrcPerThread;  // 512
constexpr int kChunks = kN / kSrcPerBlock;              // 16
constexpr int kBlocks = kChunks * kB * 2;               // 128
constexpr int kTile = 2048;                             // dst points per smem tile
constexpr int kPairs = kTile / 2;                       // 1024 packed dst pairs
constexpr int kTiles = kN / kTile;                      // 4
}  // namespace

__device__ float g_partials[kBlocks];

__device__ __forceinline__ unsigned long long pack2(float lo, float hi) {
    unsigned long long r;
    asm("mov.b64 %0, {%1, %2};" : "=l"(r) : "f"(lo), "f"(hi));
    return r;
}
__device__ __forceinline__ void unpack2(unsigned long long v, float& lo, float& hi) {
    asm("mov.b64 {%0, %1}, %2;" : "=f"(lo), "=f"(hi) : "l"(v));
}
__device__ __forceinline__ unsigned long long mul2(unsigned long long a, unsigned long long b) {
    unsigned long long d;
    asm("mul.rn.f32x2 %0, %1, %2;" : "=l"(d) : "l"(a), "l"(b));
    return d;
}
__device__ __forceinline__ unsigned long long fma2(unsigned long long a, unsigned long long b,
                                                   unsigned long long c) {
    unsigned long long d;
    asm("fma.rn.f32x2 %0, %1, %2, %3;" : "=l"(d) : "l"(a), "l"(b), "l"(c));
    return d;
}

__global__ void __launch_bounds__(kThreads, 1)
chamfer_dir_kernel(const float* __restrict__ f, const float* __restrict__ f_) {
    // Paired dst tile: sA[jp] = {pack(x0,x1), pack(y0,y1)},
    //                  sB[jp] = {pack(z0,z1), pack(w0,w1)}   (w = ||p||^2)
    __shared__ ulonglong2 sA[kPairs];
    __shared__ ulonglong2 sB[kPairs];
    __shared__ float swsum[kThreads / 32];

    const int dir = blockIdx.z;
    const int b = blockIdx.y;
    const int chunk = blockIdx.x;

    const float* src = (dir == 0) ? f : f_;
    const float* dst = (dir == 0) ? f_ : f;
    src += (size_t)b * kN * 3;
    dst += (size_t)b * kN * 3;

    const int tid = threadIdx.x;

    // Load this thread's src points; build loop-invariant replicated packs.
    unsigned long long sxx[kSrcPerThread], syy[kSrcPerThread], szz[kSrcPerThread];
    float s2[kSrcPerThread];
    float m0[kSrcPerThread], m1[kSrcPerThread];  // mins over even / odd dst
#pragma unroll
    for (int i = 0; i < kSrcPerThread; ++i) {
        const int n = chunk * kSrcPerBlock + i * kThreads + tid;
        const float x = src[n * 3 + 0];
        const float y = src[n * 3 + 1];
        const float z = src[n * 3 + 2];
        sxx[i] = pack2(x, x);
        syy[i] = pack2(y, y);
        szz[i] = pack2(z, z);
        s2[i] = fmaf(z, z, fmaf(y, y, x * x));
        m0[i] = 3.4e38f;
        m1[i] = 3.4e38f;
    }

    for (int t = 0; t < kTiles; ++t) {
        const float* dt = dst + (size_t)t * kTile * 3;
        for (int jp = tid; jp < kPairs; jp += kThreads) {
            const float x0 = dt[jp * 6 + 0];
            const float y0 = dt[jp * 6 + 1];
            const float z0 = dt[jp * 6 + 2];
            const float x1 = dt[jp * 6 + 3];
            const float y1 = dt[jp * 6 + 4];
            const float z1 = dt[jp * 6 + 5];
            const float w0 = fmaf(z0, z0, fmaf(y0, y0, x0 * x0));
            const float w1 = fmaf(z1, z1, fmaf(y1, y1, x1 * x1));
            sA[jp] = make_ulonglong2(pack2(x0, x1), pack2(y0, y1));
            sB[jp] = make_ulonglong2(pack2(z0, z1), pack2(w0, w1));
        }
        __syncthreads();

#pragma unroll 8
        for (int jp = 0; jp < kPairs; ++jp) {
            const ulonglong2 A = sA[jp];  // broadcast LDS.128, conflict-free
            const ulonglong2 B = sB[jp];
            float w0, w1;
            unpack2(B.y, w0, w1);  // register renaming, no SASS
#pragma unroll
            for (int i = 0; i < kSrcPerThread; ++i) {
                unsigned long long c = mul2(A.x, sxx[i]);   // rt2
                c = fma2(A.y, syy[i], c);                   // rt3
                c = fma2(B.x, szz[i], c);                   // rt3
                float c0, c1;
                unpack2(c, c0, c1);                         // free
                const float h0 = fmaf(c0, -2.0f, w0);       // FFMA-imm rt1
                const float h1 = fmaf(c1, -2.0f, w1);       // FFMA-imm rt1
                m0[i] = fminf(m0[i], h0);                   // alu pipe
                m1[i] = fminf(m1[i], h1);
            }
        }
        __syncthreads();
    }

    float v = 0.0f;
#pragma unroll
    for (int i = 0; i < kSrcPerThread; ++i) {
        const float mi = fminf(m0[i], m1[i]);
        v += fmaxf(s2[i] + mi, 0.0f);
    }

#pragma unroll
    for (int off = 16; off > 0; off >>= 1) {
        v += __shfl_xor_sync(0xffffffffu, v, off);
    }
    const int lane = tid & 31;
    const int wid = tid >> 5;
    if (lane == 0) swsum[wid] = v;
    __syncthreads();
    if (tid == 0) {
        float s = 0.0f;
#pragma unroll
        for (int w = 0; w < kThreads / 32; ++w) s += swsum[w];
        g_partials[chunk + kChunks * (b + kB * dir)] = s;
    }
}

__global__ void chamfer_finalize_kernel(float* __restrict__ out) {
    if (threadIdx.x == 0) {
        float s = 0.0f;
        for (int i = 0; i < kBlocks; ++i) s += g_partials[i];
        out[0] = s / (float)(kN * kB);  // / 32768
    }
}

extern "C" void kernel_launch(void* const* d_in, const int* in_sizes, int n_in,
                              void* d_out, int out_size) {
    const float* f = (const float*)d_in[0];
    const float* f_ = (const float*)d_in[1];
    (void)in_sizes; (void)n_in; (void)out_size;

    dim3 grid(kChunks, kB, 2);
    chamfer_dir_kernel<<<grid, kThreads>>>(f, f_);
    chamfer_finalize_kernel<<<1, 32>>>((float*)d_out);
}

// round 10
// speedup vs baseline: 1.6158x; 1.0440x over previous
#include <cuda_runtime.h>

// ChamferLoss: f[4,8192,3], f_[4,8192,3] -> scalar.
// R10 = R9 resubmitted verbatim (R9 bench died to container infra, no signal).
// R4 inner math/order EXACTLY (mul2-first on A, w consumed by packed tail),
// but 4 src/thread to amortize LDS + loop overhead over 8 pairs per warp-jp.
// dst split in halves so the grid stays at 128 blocks; per-half row results
// (s^2 + min, unclamped) combined by a reduce kernel: min -> clamp -> sum.

namespace {
constexpr int kB = 4;
constexpr int kN = 8192;
constexpr int kThreads = 256;
constexpr int kSrcPerThread = 4;
constexpr int kSrcPerBlock = kThreads * kSrcPerThread;  // 1024
constexpr int kChunks = kN / kSrcPerBlock;              // 8
constexpr int kHalves = 2;
constexpr int kDstBlk = kN / kHalves;                   // 4096
constexpr int kTile = 2048;                             // dst per smem tile
constexpr int kPairs = kTile / 2;                       // 1024 packed pairs
constexpr int kTilesBlk = kDstBlk / kTile;              // 2
constexpr int kRBlocks = 128;
constexpr float kBig = 3.4e38f;
}  // namespace

// [dir][b][half][n] : s^2 + min_over_half (unclamped)
__device__ float g_rowm[2 * kB * kHalves * kN];
__device__ float g_pblk[kRBlocks];

__device__ __forceinline__ unsigned long long pack2(float lo, float hi) {
    unsigned long long r;
    asm("mov.b64 %0, {%1, %2};" : "=l"(r) : "f"(lo), "f"(hi));
    return r;
}
__device__ __forceinline__ void unpack2(unsigned long long v, float& lo, float& hi) {
    asm("mov.b64 {%0, %1}, %2;" : "=f"(lo), "=f"(hi) : "l"(v));
}
__device__ __forceinline__ unsigned long long mul2(unsigned long long a, unsigned long long b) {
    unsigned long long d;
    asm("mul.rn.f32x2 %0, %1, %2;" : "=l"(d) : "l"(a), "l"(b));
    return d;
}
__device__ __forceinline__ unsigned long long fma2(unsigned long long a, unsigned long long b,
                                                   unsigned long long c) {
    unsigned long long d;
    asm("fma.rn.f32x2 %0, %1, %2, %3;" : "=l"(d) : "l"(a), "l"(b), "l"(c));
    return d;
}

__global__ void __launch_bounds__(kThreads, 1)
chamfer_dir_kernel(const float* __restrict__ f, const float* __restrict__ f_) {
    // Paired dst tile: sA[jp] = {pack(x0,x1), pack(y0,y1)},
    //                  sB[jp] = {pack(z0,z1), pack(w0,w1)}   (w = ||p||^2)
    __shared__ ulonglong2 sA[kPairs];
    __shared__ ulonglong2 sB[kPairs];

    const int chunk = blockIdx.x;            // 0..7  src chunk
    const int h = blockIdx.y;                // 0..1  dst half
    const int bd = blockIdx.z;               // 0..7  = b*2 + dir
    const int b = bd >> 1;
    const int dir = bd & 1;

    const float* src = (dir == 0) ? f : f_;
    const float* dst = (dir == 0) ? f_ : f;
    src += (size_t)b * kN * 3;
    dst += (size_t)b * kN * 3;

    const int tid = threadIdx.x;

    unsigned long long sxx[kSrcPerThread], syy[kSrcPerThread], szz[kSrcPerThread];
    float s2[kSrcPerThread];
    float m0[kSrcPerThread], m1[kSrcPerThread];
#pragma unroll
    for (int i = 0; i < kSrcPerThread; ++i) {
        const int n = chunk * kSrcPerBlock + i * kThreads + tid;
        const float x = src[n * 3 + 0];
        const float y = src[n * 3 + 1];
        const float z = src[n * 3 + 2];
        sxx[i] = pack2(x, x);
        syy[i] = pack2(y, y);
        szz[i] = pack2(z, z);
        s2[i] = fmaf(z, z, fmaf(y, y, x * x));
        m0[i] = kBig;
        m1[i] = kBig;
    }
    const unsigned long long neg2 = pack2(-2.0f, -2.0f);

    for (int t = 0; t < kTilesBlk; ++t) {
        const float* dt = dst + (size_t)(h * kDstBlk + t * kTile) * 3;
        for (int jp = tid; jp < kPairs; jp += kThreads) {
            const float x0 = dt[jp * 6 + 0];
            const float y0 = dt[jp * 6 + 1];
            const float z0 = dt[jp * 6 + 2];
            const float x1 = dt[jp * 6 + 3];
            const float y1 = dt[jp * 6 + 4];
            const float z1 = dt[jp * 6 + 5];
            const float w0 = fmaf(z0, z0, fmaf(y0, y0, x0 * x0));
            const float w1 = fmaf(z1, z1, fmaf(y1, y1, x1 * x1));
            sA[jp] = make_ulonglong2(pack2(x0, x1), pack2(y0, y1));
            sB[jp] = make_ulonglong2(pack2(z0, z1), pack2(w0, w1));
        }
        __syncthreads();

#pragma unroll 4
        for (int jp = 0; jp < kPairs; ++jp) {
            const ulonglong2 A = sA[jp];  // broadcast LDS.128, conflict-free
            const ulonglong2 B = sB[jp];
#pragma unroll
            for (int i = 0; i < kSrcPerThread; ++i) {
                unsigned long long c = mul2(A.x, sxx[i]);   // depends on A only
                c = fma2(A.y, syy[i], c);                   // A only
                c = fma2(B.x, szz[i], c);                   // B consumed late
                const unsigned long long tv = fma2(c, neg2, B.y);  // w - 2*cross
                float t0, t1;
                unpack2(tv, t0, t1);
                m0[i] = fminf(m0[i], t0);
                m1[i] = fminf(m1[i], t1);
            }
        }
        __syncthreads();
    }

    // Per-half row result: s^2 + min over this half's dst (UNCLAMPED).
#pragma unroll
    for (int i = 0; i < kSrcPerThread; ++i) {
        const int n = chunk * kSrcPerBlock + i * kThreads + tid;
        const float v = s2[i] + fminf(m0[i], m1[i]);
        g_rowm[(((size_t)dir * kB + b) * kHalves + h) * kN + n] = v;
    }
}

// Combine halves (min), clamp, per-block deterministic partial sum.
__global__ void chamfer_reduceA_kernel() {
    __shared__ float swsum[kThreads / 32];
    const int k = blockIdx.x;
    const int tid = threadIdx.x;
    const int e = k * kThreads + tid;      // 0..32767 = (b,n)
    const int b = e >> 13;
    const int n = e & (kN - 1);

    float acc = 0.0f;
#pragma unroll
    for (int dir = 0; dir < 2; ++dir) {
        const size_t base = (((size_t)dir * kB + b) * kHalves) * kN + n;
        const float v = fminf(g_rowm[base], g_rowm[base + kN]);
        acc += fmaxf(v, 0.0f);
    }

#pragma unroll
    for (int off = 16; off > 0; off >>= 1) {
        acc += __shfl_xor_sync(0xffffffffu, acc, off);
    }
    if ((tid & 31) == 0) swsum[tid >> 5] = acc;
    __syncthreads();
    if (tid == 0) {
        float t = 0.0f;
#pragma unroll
        for (int w = 0; w < kThreads / 32; ++w) t += swsum[w];
        g_pblk[k] = t;
    }
}

__global__ void chamfer_reduceB_kernel(float* __restrict__ out) {
    __shared__ float sw[4];
    const int tid = threadIdx.x;  // 128
    float v = g_pblk[tid];
#pragma unroll
    for (int off = 16; off > 0; off >>= 1) {
        v += __shfl_xor_sync(0xffffffffu, v, off);
    }
    if ((tid & 31) == 0) sw[tid >> 5] = v;
    __syncthreads();
    if (tid == 0) {
        out[0] = ((sw[0] + sw[1]) + (sw[2] + sw[3])) / (float)(kN * kB);
    }
}

extern "C" void kernel_launch(void* const* d_in, const int* in_sizes, int n_in,
                              void* d_out, int out_size) {
    const float* f = (const float*)d_in[0];
    const float* f_ = (const float*)d_in[1];
    (void)in_sizes; (void)n_in; (void)out_size;

    dim3 grid(kChunks, kHalves, kB * 2);   // 8 x 2 x 8 = 128 blocks
    chamfer_dir_kernel<<<grid, kThreads>>>(f, f_);
    chamfer_reduceA_kernel<<<kRBlocks, kThreads>>>();
    chamfer_reduceB_kernel<<<1, 128>>>((float*)d_out);
}

// round 11
// speedup vs baseline: 1.6734x; 1.0356x over previous
#include <cuda_runtime.h>

// ChamferLoss: f[4,8192,3], f_[4,8192,3] -> scalar.
// R11 = R10 inner loop byte-identical; dst split into QUARTERS -> 256 blocks
// -> 2 CTAs/SM -> 4 warps/SMSP for latency hiding (R10 profile: issue=58.8%,
// fma=55.6%, occ=12.5% -- stall-limited, not width-limited).
// Per-quarter row results (s^2 + min, unclamped) merged min->clamp->sum.

namespace {
constexpr int kB = 4;
constexpr int kN = 8192;
constexpr int kThreads = 256;
constexpr int kSrcPerThread = 4;
constexpr int kSrcPerBlock = kThreads * kSrcPerThread;  // 1024
constexpr int kChunks = kN / kSrcPerBlock;              // 8
constexpr int kQuarters = 4;
constexpr int kDstBlk = kN / kQuarters;                 // 2048 = one tile
constexpr int kPairs = kDstBlk / 2;                     // 1024 packed pairs
constexpr int kRBlocks = 128;
constexpr float kBig = 3.4e38f;
}  // namespace

// [dir][b][quarter][n] : s^2 + min_over_quarter (unclamped)
__device__ float g_rowm[2 * kB * kQuarters * kN];
__device__ float g_pblk[kRBlocks];

__device__ __forceinline__ unsigned long long pack2(float lo, float hi) {
    unsigned long long r;
    asm("mov.b64 %0, {%1, %2};" : "=l"(r) : "f"(lo), "f"(hi));
    return r;
}
__device__ __forceinline__ void unpack2(unsigned long long v, float& lo, float& hi) {
    asm("mov.b64 {%0, %1}, %2;" : "=f"(lo), "=f"(hi) : "l"(v));
}
__device__ __forceinline__ unsigned long long mul2(unsigned long long a, unsigned long long b) {
    unsigned long long d;
    asm("mul.rn.f32x2 %0, %1, %2;" : "=l"(d) : "l"(a), "l"(b));
    return d;
}
__device__ __forceinline__ unsigned long long fma2(unsigned long long a, unsigned long long b,
                                                   unsigned long long c) {
    unsigned long long d;
    asm("fma.rn.f32x2 %0, %1, %2, %3;" : "=l"(d) : "l"(a), "l"(b), "l"(c));
    return d;
}

__global__ void __launch_bounds__(kThreads, 2)
chamfer_dir_kernel(const float* __restrict__ f, const float* __restrict__ f_) {
    // Paired dst tile: sA[jp] = {pack(x0,x1), pack(y0,y1)},
    //                  sB[jp] = {pack(z0,z1), pack(w0,w1)}   (w = ||p||^2)
    __shared__ ulonglong2 sA[kPairs];
    __shared__ ulonglong2 sB[kPairs];

    const int chunk = blockIdx.x;            // 0..7  src chunk
    const int q = blockIdx.y;                // 0..3  dst quarter
    const int bd = blockIdx.z;               // 0..7  = b*2 + dir
    const int b = bd >> 1;
    const int dir = bd & 1;

    const float* src = (dir == 0) ? f : f_;
    const float* dst = (dir == 0) ? f_ : f;
    src += (size_t)b * kN * 3;
    dst += (size_t)b * kN * 3;

    const int tid = threadIdx.x;

    unsigned long long sxx[kSrcPerThread], syy[kSrcPerThread], szz[kSrcPerThread];
    float s2[kSrcPerThread];
    float m0[kSrcPerThread], m1[kSrcPerThread];
#pragma unroll
    for (int i = 0; i < kSrcPerThread; ++i) {
        const int n = chunk * kSrcPerBlock + i * kThreads + tid;
        const float x = src[n * 3 + 0];
        const float y = src[n * 3 + 1];
        const float z = src[n * 3 + 2];
        sxx[i] = pack2(x, x);
        syy[i] = pack2(y, y);
        szz[i] = pack2(z, z);
        s2[i] = fmaf(z, z, fmaf(y, y, x * x));
        m0[i] = kBig;
        m1[i] = kBig;
    }
    const unsigned long long neg2 = pack2(-2.0f, -2.0f);

    // One tile fill: this block's dst quarter.
    {
        const float* dt = dst + (size_t)(q * kDstBlk) * 3;
        for (int jp = tid; jp < kPairs; jp += kThreads) {
            const float x0 = dt[jp * 6 + 0];
            const float y0 = dt[jp * 6 + 1];
            const float z0 = dt[jp * 6 + 2];
            const float x1 = dt[jp * 6 + 3];
            const float y1 = dt[jp * 6 + 4];
            const float z1 = dt[jp * 6 + 5];
            const float w0 = fmaf(z0, z0, fmaf(y0, y0, x0 * x0));
            const float w1 = fmaf(z1, z1, fmaf(y1, y1, x1 * x1));
            sA[jp] = make_ulonglong2(pack2(x0, x1), pack2(y0, y1));
            sB[jp] = make_ulonglong2(pack2(z0, z1), pack2(w0, w1));
        }
        __syncthreads();
    }

#pragma unroll 4
    for (int jp = 0; jp < kPairs; ++jp) {
        const ulonglong2 A = sA[jp];  // broadcast LDS.128, conflict-free
        const ulonglong2 B = sB[jp];
#pragma unroll
        for (int i = 0; i < kSrcPerThread; ++i) {
            unsigned long long c = mul2(A.x, sxx[i]);   // depends on A only
            c = fma2(A.y, syy[i], c);                   // A only
            c = fma2(B.x, szz[i], c);                   // B consumed late
            const unsigned long long tv = fma2(c, neg2, B.y);  // w - 2*cross
            float t0, t1;
            unpack2(tv, t0, t1);
            m0[i] = fminf(m0[i], t0);
            m1[i] = fminf(m1[i], t1);
        }
    }

    // Per-quarter row result: s^2 + min over this quarter's dst (UNCLAMPED).
#pragma unroll
    for (int i = 0; i < kSrcPerThread; ++i) {
        const int n = chunk * kSrcPerBlock + i * kThreads + tid;
        const float v = s2[i] + fminf(m0[i], m1[i]);
        g_rowm[(((size_t)dir * kB + b) * kQuarters + q) * kN + n] = v;
    }
}

// Combine quarters (min), clamp, per-block deterministic partial sum.
__global__ void chamfer_reduceA_kernel() {
    __shared__ float swsum[kThreads / 32];
    const int k = blockIdx.x;
    const int tid = threadIdx.x;
    const int e = k * kThreads + tid;      // 0..32767 = (b,n)
    const int b = e >> 13;
    const int n = e & (kN - 1);

    float acc = 0.0f;
#pragma unroll
    for (int dir = 0; dir < 2; ++dir) {
        const size_t base = (((size_t)dir * kB + b) * kQuarters) * kN + n;
        float v = fminf(g_rowm[base], g_rowm[base + kN]);
        v = fminf(v, g_rowm[base + 2 * (size_t)kN]);
        v = fminf(v, g_rowm[base + 3 * (size_t)kN]);
        acc += fmaxf(v, 0.0f);
    }

#pragma unroll
    for (int off = 16; off > 0; off >>= 1) {
        acc += __shfl_xor_sync(0xffffffffu, acc, off);
    }
    if ((tid & 31) == 0) swsum[tid >> 5] = acc;
    __syncthreads();
    if (tid == 0) {
        float t = 0.0f;
#pragma unroll
        for (int w = 0; w < kThreads / 32; ++w) t += swsum[w];
        g_pblk[k] = t;
    }
}

__global__ void chamfer_reduceB_kernel(float* __restrict__ out) {
    __shared__ float sw[4];
    const int tid = threadIdx.x;  // 128
    float v = g_pblk[tid];
#pragma unroll
    for (int off = 16; off > 0; off >>= 1) {
        v += __shfl_xor_sync(0xffffffffu, v, off);
    }
    if ((tid & 31) == 0) sw[tid >> 5] = v;
    __syncthreads();
    if (tid == 0) {
        out[0] = ((sw[0] + sw[1]) + (sw[2] + sw[3])) / (float)(kN * kB);
    }
}

extern "C" void kernel_launch(void* const* d_in, const int* in_sizes, int n_in,
                              void* d_out, int out_size) {
    const float* f = (const float*)d_in[0];
    const float* f_ = (const float*)d_in[1];
    (void)in_sizes; (void)n_in; (void)out_size;

    dim3 grid(kChunks, kQuarters, kB * 2);   // 8 x 4 x 8 = 256 blocks
    chamfer_dir_kernel<<<grid, kThreads>>>(f, f_);
    chamfer_reduceA_kernel<<<kRBlocks, kThreads>>>();
    chamfer_reduceB_kernel<<<1, 128>>>((float*)d_out);
}

// round 13
// speedup vs baseline: 1.8764x; 1.1213x over previous
#include <cuda_runtime.h>

// ChamferLoss: f[4,8192,3], f_[4,8192,3] -> scalar.
// R13 = R12 resubmitted verbatim (R12 bench died to container infra, no signal).
// R11 envelope exactly (256 blocks, 4 src/thread, 2 CTAs/SM, quarters)
// with the minimal 3-fma2 inner chain: -2 folded into the SRC register packs,
// w = ||p||^2 as the chain's initial addend:
//   c = fma2(A.x, -2sx, w); c = fma2(A.y, -2sy, c); c = fma2(B.x, -2sz, c)
// (R7 ran this chain but at 2 src + 2 warps/SMSP and died on chain-head LDS
// latency; here 16 chains/SMSP are in flight to cover it.)

namespace {
constexpr int kB = 4;
constexpr int kN = 8192;
constexpr int kThreads = 256;
constexpr int kSrcPerThread = 4;
constexpr int kSrcPerBlock = kThreads * kSrcPerThread;  // 1024
constexpr int kChunks = kN / kSrcPerBlock;              // 8
constexpr int kQuarters = 4;
constexpr int kDstBlk = kN / kQuarters;                 // 2048 = one tile
constexpr int kPairs = kDstBlk / 2;                     // 1024 packed pairs
constexpr int kRBlocks = 128;
constexpr float kBig = 3.4e38f;
}  // namespace

// [dir][b][quarter][n] : s^2 + min_over_quarter (unclamped)
__device__ float g_rowm[2 * kB * kQuarters * kN];
__device__ float g_pblk[kRBlocks];

__device__ __forceinline__ unsigned long long pack2(float lo, float hi) {
    unsigned long long r;
    asm("mov.b64 %0, {%1, %2};" : "=l"(r) : "f"(lo), "f"(hi));
    return r;
}
__device__ __forceinline__ void unpack2(unsigned long long v, float& lo, float& hi) {
    asm("mov.b64 {%0, %1}, %2;" : "=f"(lo), "=f"(hi) : "l"(v));
}
__device__ __forceinline__ unsigned long long fma2(unsigned long long a, unsigned long long b,
                                                   unsigned long long c) {
    unsigned long long d;
    asm("fma.rn.f32x2 %0, %1, %2, %3;" : "=l"(d) : "l"(a), "l"(b), "l"(c));
    return d;
}

__global__ void __launch_bounds__(kThreads, 2)
chamfer_dir_kernel(const float* __restrict__ f, const float* __restrict__ f_) {
    // Paired dst tile: sA[jp] = {pack(x0,x1), pack(y0,y1)},
    //                  sB[jp] = {pack(z0,z1), pack(w0,w1)}   (w = ||p||^2)
    __shared__ ulonglong2 sA[kPairs];
    __shared__ ulonglong2 sB[kPairs];

    const int chunk = blockIdx.x;            // 0..7  src chunk
    const int q = blockIdx.y;                // 0..3  dst quarter
    const int bd = blockIdx.z;               // 0..7  = b*2 + dir
    const int b = bd >> 1;
    const int dir = bd & 1;

    const float* src = (dir == 0) ? f : f_;
    const float* dst = (dir == 0) ? f_ : f;
    src += (size_t)b * kN * 3;
    dst += (size_t)b * kN * 3;

    const int tid = threadIdx.x;

    // Src packs with -2 folded in (free: done once per thread).
    unsigned long long sxx[kSrcPerThread], syy[kSrcPerThread], szz[kSrcPerThread];
    float s2[kSrcPerThread];
    float m0[kSrcPerThread], m1[kSrcPerThread];
#pragma unroll
    for (int i = 0; i < kSrcPerThread; ++i) {
        const int n = chunk * kSrcPerBlock + i * kThreads + tid;
        const float x = src[n * 3 + 0];
        const float y = src[n * 3 + 1];
        const float z = src[n * 3 + 2];
        const float mx = -2.0f * x, my = -2.0f * y, mz = -2.0f * z;
        sxx[i] = pack2(mx, mx);
        syy[i] = pack2(my, my);
        szz[i] = pack2(mz, mz);
        s2[i] = fmaf(z, z, fmaf(y, y, x * x));
        m0[i] = kBig;
        m1[i] = kBig;
    }

    // One tile fill: this block's dst quarter.
    {
        const float* dt = dst + (size_t)(q * kDstBlk) * 3;
        for (int jp = tid; jp < kPairs; jp += kThreads) {
            const float x0 = dt[jp * 6 + 0];
            const float y0 = dt[jp * 6 + 1];
            const float z0 = dt[jp * 6 + 2];
            const float x1 = dt[jp * 6 + 3];
            const float y1 = dt[jp * 6 + 4];
            const float z1 = dt[jp * 6 + 5];
            const float w0 = fmaf(z0, z0, fmaf(y0, y0, x0 * x0));
            const float w1 = fmaf(z1, z1, fmaf(y1, y1, x1 * x1));
            sA[jp] = make_ulonglong2(pack2(x0, x1), pack2(y0, y1));
            sB[jp] = make_ulonglong2(pack2(z0, z1), pack2(w0, w1));
        }
        __syncthreads();
    }

#pragma unroll 4
    for (int jp = 0; jp < kPairs; ++jp) {
        const ulonglong2 A = sA[jp];  // broadcast LDS.128, conflict-free
        const ulonglong2 B = sB[jp];
#pragma unroll
        for (int i = 0; i < kSrcPerThread; ++i) {
            unsigned long long c = fma2(A.x, sxx[i], B.y);  // w - 2x*sx
            c = fma2(A.y, syy[i], c);                       // .. - 2y*sy
            c = fma2(B.x, szz[i], c);                       // .. - 2z*sz
            float t0, t1;
            unpack2(c, t0, t1);
            m0[i] = fminf(m0[i], t0);
            m1[i] = fminf(m1[i], t1);
        }
    }

    // Per-quarter row result: s^2 + min over this quarter's dst (UNCLAMPED).
#pragma unroll
    for (int i = 0; i < kSrcPerThread; ++i) {
        const int n = chunk * kSrcPerBlock + i * kThreads + tid;
        const float v = s2[i] + fminf(m0[i], m1[i]);
        g_rowm[(((size_t)dir * kB + b) * kQuarters + q) * kN + n] = v;
    }
}

// Combine quarters (min), clamp, per-block deterministic partial sum.
__global__ void chamfer_reduceA_kernel() {
    __shared__ float swsum[kThreads / 32];
    const int k = blockIdx.x;
    const int tid = threadIdx.x;
    const int e = k * kThreads + tid;      // 0..32767 = (b,n)
    const int b = e >> 13;
    const int n = e & (kN - 1);

    float acc = 0.0f;
#pragma unroll
    for (int dir = 0; dir < 2; ++dir) {
        const size_t base = (((size_t)dir * kB + b) * kQuarters) * kN + n;
        float v = fminf(g_rowm[base], g_rowm[base + kN]);
        v = fminf(v, g_rowm[base + 2 * (size_t)kN]);
        v = fminf(v, g_rowm[base + 3 * (size_t)kN]);
        acc += fmaxf(v, 0.0f);
    }

#pragma unroll
    for (int off = 16; off > 0; off >>= 1) {
        acc += __shfl_xor_sync(0xffffffffu, acc, off);
    }
    if ((tid & 31) == 0) swsum[tid >> 5] = acc;
    __syncthreads();
    if (tid == 0) {
        float t = 0.0f;
#pragma unroll
        for (int w = 0; w < kThreads / 32; ++w) t += swsum[w];
        g_pblk[k] = t;
    }
}

__global__ void chamfer_reduceB_kernel(float* __restrict__ out) {
    __shared__ float sw[4];
    const int tid = threadIdx.x;  // 128
    float v = g_pblk[tid];
#pragma unroll
    for (int off = 16; off > 0; off >>= 1) {
        v += __shfl_xor_sync(0xffffffffu, v, off);
    }
    if ((tid & 31) == 0) sw[tid >> 5] = v;
    __syncthreads();
    if (tid == 0) {
        out[0] = ((sw[0] + sw[1]) + (sw[2] + sw[3])) / (float)(kN * kB);
    }
}

extern "C" void kernel_launch(void* const* d_in, const int* in_sizes, int n_in,
                              void* d_out, int out_size) {
    const float* f = (const float*)d_in[0];
    const float* f_ = (const float*)d_in[1];
    (void)in_sizes; (void)n_in; (void)out_size;

    dim3 grid(kChunks, kQuarters, kB * 2);   // 8 x 4 x 8 = 256 blocks
    chamfer_dir_kernel<<<grid, kThreads>>>(f, f_);
    chamfer_reduceA_kernel<<<kRBlocks, kThreads>>>();
    chamfer_reduceB_kernel<<<1, 128>>>((float*)d_out);
}